// round 7
// baseline (speedup 1.0000x reference)
#include <cuda_runtime.h>
#include <cuda_fp16.h>
#include <math.h>
#include <stdint.h>

#define BB 4
#define NTOK 4096
#define CC 256
#define BNTOK (BB * NTOK)   // 16384

// ---------------- static scratch ----------------
__device__ float  gQ  [(size_t)BNTOK * CC];          // fp32 Q for dwconv
__device__ __half gQh [(size_t)BNTOK * CC];
__device__ __half gKh [(size_t)BNTOK * CC];
__device__ __half gVh [(size_t)BNTOK * CC];
__device__ float  gZ  [(size_t)BNTOK * CC];
__device__ float  gPE [(size_t)BNTOK * CC];
__device__ __half gTh [(size_t)BNTOK * CC];
__device__ __half gXh [(size_t)BNTOK * CC];
__device__ __half gWqkvh[CC * 3 * CC];
__device__ __half gWgateh[CC * CC];
__device__ __half gWprojh[CC * CC];

__device__ __forceinline__ void cpa16(uint32_t dst, const void* src) {
    asm volatile("cp.async.ca.shared.global [%0], [%1], 16;" :: "r"(dst), "l"(src));
}
__device__ __forceinline__ void ldmx4(uint32_t r[4], uint32_t addr) {
    asm volatile("ldmatrix.sync.aligned.m8n8.x4.shared.b16 {%0,%1,%2,%3}, [%4];"
                 : "=r"(r[0]), "=r"(r[1]), "=r"(r[2]), "=r"(r[3]) : "r"(addr));
}
__device__ __forceinline__ void ldmx4t(uint32_t r[4], uint32_t addr) {
    asm volatile("ldmatrix.sync.aligned.m8n8.x4.trans.shared.b16 {%0,%1,%2,%3}, [%4];"
                 : "=r"(r[0]), "=r"(r[1]), "=r"(r[2]), "=r"(r[3]) : "r"(addr));
}
__device__ __forceinline__ void ldmx2(uint32_t r[2], uint32_t addr) {
    asm volatile("ldmatrix.sync.aligned.m8n8.x2.shared.b16 {%0,%1}, [%2];"
                 : "=r"(r[0]), "=r"(r[1]) : "r"(addr));
}
__device__ __forceinline__ void ldmx2t(uint32_t r[2], uint32_t addr) {
    asm volatile("ldmatrix.sync.aligned.m8n8.x2.trans.shared.b16 {%0,%1}, [%2];"
                 : "=r"(r[0]), "=r"(r[1]) : "r"(addr));
}
__device__ __forceinline__ void mma_f16(float d[4], const uint32_t a[4],
                                        uint32_t b0, uint32_t b1) {
    asm volatile(
        "mma.sync.aligned.m16n8k16.row.col.f32.f16.f16.f32 "
        "{%0,%1,%2,%3}, {%4,%5,%6,%7}, {%8,%9}, {%0,%1,%2,%3};"
        : "+f"(d[0]), "+f"(d[1]), "+f"(d[2]), "+f"(d[3])
        : "r"(a[0]), "r"(a[1]), "r"(a[2]), "r"(a[3]), "r"(b0), "r"(b1));
}
__device__ __forceinline__ void waitN(int n) {
    if (n >= 2)      asm volatile("cp.async.wait_group 2;");
    else if (n == 1) asm volatile("cp.async.wait_group 1;");
    else             asm volatile("cp.async.wait_group 0;");
}

// ======================================================================
// Flash attention: gTh = ((softmax(Q K^T * s) V) + PE) * Z, unstabilized.
// Per CTA: 64 Q rows; loop over 32 KV blocks of 128.
// 8 warps (wm 2 x wn 4). Stage1 warp tile 32x32 (S), stage2 32x64 (O).
// Unified cp.async ring: 12 chunks/KV-block (8 K-chunks of 32k, 4 V-chunks of 32kv).
// ======================================================================
#define QSTR 264      // Q smem row stride (halves)
#define ESTR 136      // E smem row stride
#define VSTR 264      // V stage row stride
#define KSTR 40       // K stage row stride
#define STAGE_B 16896 // bytes per ring slot (max of K:10240, V:16896)
#define OFF_Q 0                        // 64*264*2 = 33792
#define OFF_E 33792                    // 64*136*2 = 17408
#define OFF_S 51200                    // 4*16896  = 67584
#define OFF_L 118784                   // 64 floats
#define FSMEM (118784 + 256)

__global__ void __launch_bounds__(256, 1)
flash_attn()
{
    extern __shared__ __align__(16) char sm[];
    const uint32_t smb = (uint32_t)__cvta_generic_to_shared(sm);
    const int tid = threadIdx.x;
    const int lane = tid & 31, wid = tid >> 5;
    const int g = lane >> 2, t = lane & 3;
    const int wm = wid >> 2, wn = wid & 3;
    const int qBase = blockIdx.x * 64;
    const int bz = blockIdx.y;

    const __half* Qg = gQh + ((size_t)bz * NTOK + qBase) * CC;
    const __half* Kg = gKh + (size_t)bz * NTOK * CC;
    const __half* Vg = gVh + (size_t)bz * NTOK * CC;
    float* Lred = (float*)(sm + OFF_L);
    if (tid < 64) Lred[tid] = 0.0f;

    // Q resident load: 64 rows x 512 B
    #pragma unroll
    for (int j = 0; j < 8; j++) {
        const int task = tid + j * 256;
        const int row = task >> 5, ch = task & 31;
        cpa16(smb + OFF_Q + (row * QSTR + ch * 8) * 2, Qg + (size_t)row * CC + ch * 8);
    }
    asm volatile("cp.async.commit_group;");

    auto loadChunk = [&](int cg) {
        const int j = cg / 12, i = cg % 12;
        const uint32_t buf = smb + OFF_S + (cg & 3) * STAGE_B;
        const int kvBase = j * 128;
        if (i < 8) {          // K chunk: 128 kv rows x 32 k-halves
            #pragma unroll
            for (int u = 0; u < 2; u++) {
                const int task = tid + u * 256;
                const int row = task >> 2, ch = task & 3;
                cpa16(buf + (row * KSTR + ch * 8) * 2,
                      Kg + (size_t)(kvBase + row) * CC + i * 32 + ch * 8);
            }
        } else {              // V chunk: 32 kv rows x 256 c-halves
            const int v0 = (i - 8) * 32;
            #pragma unroll
            for (int u = 0; u < 4; u++) {
                const int task = tid + u * 256;
                const int row = task >> 5, ch = task & 31;
                cpa16(buf + (row * VSTR + ch * 8) * 2,
                      Vg + (size_t)(kvBase + v0 + row) * CC + ch * 8);
            }
        }
        asm volatile("cp.async.commit_group;");
    };

    loadChunk(0); loadChunk(1); loadChunk(2);

    float o[2][8][4];
    #pragma unroll
    for (int mi = 0; mi < 2; mi++)
        #pragma unroll
        for (int ni = 0; ni < 8; ni++)
            #pragma unroll
            for (int q = 0; q < 4; q++) o[mi][ni][q] = 0.0f;
    float rsum[4] = {0.0f, 0.0f, 0.0f, 0.0f};

    const uint32_t qB = smb + OFF_Q;
    const uint32_t eB = smb + OFF_E;
    const int TOTAL = 32 * 12;

    for (int j = 0; j < 32; j++) {
        float s[2][4][4];
        #pragma unroll
        for (int mi = 0; mi < 2; mi++)
            #pragma unroll
            for (int ni = 0; ni < 4; ni++)
                #pragma unroll
                for (int q = 0; q < 4; q++) s[mi][ni][q] = 0.0f;

        // ---- phase A: S = Q K_j^T over 8 K chunks ----
        for (int i = 0; i < 8; i++) {
            const int cg = j * 12 + i;
            waitN(TOTAL - 1 - cg);
            __syncthreads();
            if (cg + 3 < TOTAL) loadChunk(cg + 3);
            const uint32_t kb = smb + OFF_S + (cg & 3) * STAGE_B;
            #pragma unroll
            for (int ss = 0; ss < 2; ss++) {
                const int k0 = i * 32 + ss * 16;
                uint32_t a[2][4];
                #pragma unroll
                for (int mi = 0; mi < 2; mi++)
                    ldmx4(a[mi], qB + ((wm * 32 + mi * 16 + (lane & 15)) * QSTR
                                       + k0 + (lane >> 4) * 8) * 2);
                #pragma unroll
                for (int ni = 0; ni < 4; ni++) {
                    uint32_t b[2];
                    ldmx2(b, kb + ((wn * 32 + ni * 8 + (lane & 7)) * KSTR
                                   + ss * 16 + ((lane >> 3) & 1) * 8) * 2);
                    #pragma unroll
                    for (int mi = 0; mi < 2; mi++)
                        mma_f16(s[mi][ni], a[mi], b[0], b[1]);
                }
            }
        }

        // ---- exp -> E smem + row-sum partials ----
        __syncthreads();   // prior stage-2 reads of E are done
        #pragma unroll
        for (int mi = 0; mi < 2; mi++)
            #pragma unroll
            for (int hf = 0; hf < 2; hf++) {
                const int row = wm * 32 + mi * 16 + g + hf * 8;
                float rs = 0.0f;
                #pragma unroll
                for (int ni = 0; ni < 4; ni++) {
                    float e0 = __expf(s[mi][ni][2 * hf + 0] * 0.0625f);
                    float e1 = __expf(s[mi][ni][2 * hf + 1] * 0.0625f);
                    __half2 hv = __floats2half2_rn(e0, e1);
                    *(__half2*)(sm + OFF_E + (row * ESTR + wn * 32 + ni * 8 + 2 * t) * 2) = hv;
                    rs += __low2float(hv) + __high2float(hv);
                }
                rsum[mi * 2 + hf] += rs;
            }
        __syncthreads();

        // ---- phase B: O += E V_j over 4 V chunks ----
        for (int i = 0; i < 4; i++) {
            const int cg = j * 12 + 8 + i;
            waitN(TOTAL - 1 - cg);
            __syncthreads();
            if (cg + 3 < TOTAL) loadChunk(cg + 3);
            const uint32_t vb = smb + OFF_S + (cg & 3) * STAGE_B;
            #pragma unroll
            for (int ss = 0; ss < 2; ss++) {
                const int k0 = i * 32 + ss * 16;
                uint32_t a[2][4];
                #pragma unroll
                for (int mi = 0; mi < 2; mi++)
                    ldmx4(a[mi], eB + ((wm * 32 + mi * 16 + (lane & 15)) * ESTR
                                       + k0 + (lane >> 4) * 8) * 2);
                #pragma unroll
                for (int nq = 0; nq < 4; nq++) {
                    uint32_t b[4];
                    ldmx4t(b, vb + ((ss * 16 + (lane & 15)) * VSTR
                                    + wn * 64 + nq * 16 + (lane >> 4) * 8) * 2);
                    #pragma unroll
                    for (int mi = 0; mi < 2; mi++) {
                        mma_f16(o[mi][2 * nq + 0], a[mi], b[0], b[1]);
                        mma_f16(o[mi][2 * nq + 1], a[mi], b[2], b[3]);
                    }
                }
            }
        }
    }

    // ---- row-sum reduce across t lanes and wn warps ----
    #pragma unroll
    for (int q = 0; q < 4; q++) {
        float v = rsum[q];
        v += __shfl_xor_sync(0xffffffffu, v, 1);
        v += __shfl_xor_sync(0xffffffffu, v, 2);
        if (t == 0) atomicAdd(&Lred[wm * 32 + (q >> 1) * 16 + g + (q & 1) * 8], v);
    }
    __syncthreads();

    // ---- epilogue: gTh = ((O/L) + PE) * Z ----
    #pragma unroll
    for (int mi = 0; mi < 2; mi++)
        #pragma unroll
        for (int hf = 0; hf < 2; hf++) {
            const int rl = wm * 32 + mi * 16 + g + hf * 8;
            const float invL = 1.0f / Lred[rl];
            const int r = qBase + rl;
            #pragma unroll
            for (int ni = 0; ni < 8; ni++) {
                const int c = wn * 64 + ni * 8 + 2 * t;
                const size_t idx = ((size_t)(bz * NTOK + r)) * CC + c;
                float2 pe = *(const float2*)&gPE[idx];
                float2 zz = *(const float2*)&gZ[idx];
                float v0 = o[mi][ni][2 * hf + 0] * invL;
                float v1 = o[mi][ni][2 * hf + 1] * invL;
                *(__half2*)&gTh[idx] = __floats2half2_rn((v0 + pe.x) * zz.x,
                                                         (v1 + pe.y) * zz.y);
            }
        }
}

// ======================================================================
// fp16 GEMM (unchanged structure) for qkv / gate / proj.
// ======================================================================
#define ASTG 10240
#define BSTG_T 8704
#define NSTAGE 4

template<int MODE>   // 0: qkv split, 1: gelu gate, 4: plain out
__global__ void __launch_bounds__(256, 2)
hgemm(const __half* __restrict__ A, const __half* __restrict__ B, float* __restrict__ Out,
      int K, int lda, int ldb, const float* __restrict__ bias)
{
    extern __shared__ __align__(16) char sm[];
    const uint32_t smb = (uint32_t)__cvta_generic_to_shared(sm);
    const uint32_t aBase = smb;
    const uint32_t bBase = smb + NSTAGE * ASTG;

    const int tid  = threadIdx.x;
    const int wid  = tid >> 5;
    const int lane = tid & 31;
    const int g    = lane >> 2;
    const int t    = lane & 3;
    const int wm   = wid >> 2;
    const int wn   = wid & 3;

    const int rowBlk = blockIdx.y * 128;
    const int colBlk = blockIdx.x * 128;
    const int NC = K >> 5;

    float d[4][4][4];
    #pragma unroll
    for (int mi = 0; mi < 4; mi++)
        #pragma unroll
        for (int ni = 0; ni < 4; ni++)
            #pragma unroll
            for (int j = 0; j < 4; j++) d[mi][ni][j] = 0.0f;

    auto loadStage = [&](int c) {
        const int kt = c << 5;
        const int sb = c & (NSTAGE - 1);
        const uint32_t aS = aBase + sb * ASTG;
        #pragma unroll
        for (int j = 0; j < 2; j++) {
            const int task = tid + j * 256;
            const int row = task >> 2, ch = task & 3;
            cpa16(aS + row * 80 + ch * 16, A + (size_t)(rowBlk + row) * lda + kt + ch * 8);
        }
        const uint32_t bS = bBase + sb * BSTG_T;
        #pragma unroll
        for (int j = 0; j < 2; j++) {
            const int task = tid + j * 256;
            const int row = task >> 4, ch = task & 15;
            cpa16(bS + row * 272 + ch * 16, B + (size_t)(kt + row) * ldb + colBlk + ch * 8);
        }
        asm volatile("cp.async.commit_group;");
    };

    loadStage(0); loadStage(1); loadStage(2);

    for (int c = 0; c < NC; ++c) {
        waitN(NC - 1 - c);
        __syncthreads();
        if (c + 3 < NC) loadStage(c + 3);

        const int sb = c & (NSTAGE - 1);
        const uint32_t aS = aBase + sb * ASTG;
        const uint32_t bS = bBase + sb * BSTG_T;

        #pragma unroll
        for (int s = 0; s < 2; s++) {
            const int k0 = 16 * s;
            uint32_t a[4][4];
            #pragma unroll
            for (int mi = 0; mi < 4; mi++)
                ldmx4(a[mi], aS + ((wm * 64 + mi * 16 + (lane & 15)) * 40
                                   + k0 + (lane >> 4) * 8) * 2);
            uint32_t b[4][2];
            #pragma unroll
            for (int ni = 0; ni < 4; ni++)
                ldmx2t(b[ni], bS + ((k0 + (lane & 15)) * 136 + wn * 32 + ni * 8) * 2);
            #pragma unroll
            for (int mi = 0; mi < 4; mi++)
                #pragma unroll
                for (int ni = 0; ni < 4; ni++)
                    mma_f16(d[mi][ni], a[mi], b[ni][0], b[ni][1]);
        }
        __syncthreads();
    }

    #pragma unroll
    for (int mi = 0; mi < 4; mi++) {
        #pragma unroll
        for (int hf = 0; hf < 2; hf++) {
            const int r = rowBlk + wm * 64 + mi * 16 + g + hf * 8;
            #pragma unroll
            for (int ni = 0; ni < 4; ni++) {
                const int c = colBlk + wn * 32 + ni * 8 + 2 * t;
                float v0 = d[mi][ni][2 * hf + 0];
                float v1 = d[mi][ni][2 * hf + 1];

                if (MODE == 0) {
                    const int seg = c >> 8;
                    const int cc = c & 255;
                    const size_t idx = (size_t)r * CC + cc;
                    __half2 hv = __floats2half2_rn(v0, v1);
                    if (seg == 0) {
                        *(float2*)&gQ[idx] = make_float2(v0, v1);
                        *(__half2*)&gQh[idx] = hv;
                    } else if (seg == 1) {
                        *(__half2*)&gKh[idx] = hv;
                    } else {
                        *(__half2*)&gVh[idx] = hv;
                    }
                } else if (MODE == 1) {
                    float2 bb = *(const float2*)&bias[c];
                    float a0 = v0 + bb.x, a1 = v1 + bb.y;
                    float2 v;
                    v.x = 0.5f * a0 * (1.0f + erff(a0 * 0.70710678118654752f));
                    v.y = 0.5f * a1 * (1.0f + erff(a1 * 0.70710678118654752f));
                    *(float2*)&gZ[(size_t)r * CC + c] = v;
                } else {
                    *(float2*)&Out[(size_t)r * CC + c] = make_float2(v0, v1);
                }
            }
        }
    }
}

// ---------------- fused convert (x + 3 weights -> fp16) ----------------
#define N2_X   (BNTOK * CC / 2)
#define N2_QKV (CC * 3 * CC / 2)
#define N2_GW  (CC * CC / 2)
__global__ void __launch_bounds__(256)
convert_all(const float* __restrict__ x, const float* __restrict__ Wqkv,
            const float* __restrict__ Wgate, const float* __restrict__ Wproj)
{
    int i = blockIdx.x * 256 + threadIdx.x;
    const float* src; __half* dst; int off;
    if (i < N2_X)                        { src = x;     dst = gXh;     off = i; }
    else if ((i -= N2_X) < N2_QKV)       { src = Wqkv;  dst = gWqkvh;  off = i; }
    else if ((i -= N2_QKV) < N2_GW)      { src = Wgate; dst = gWgateh; off = i; }
    else if ((i -= N2_GW) < N2_GW)       { src = Wproj; dst = gWprojh; off = i; }
    else return;
    float2 v = *(const float2*)(src + 2 * off);
    *(__half2*)(dst + 2 * off) = __floats2half2_rn(v.x, v.y);
}

// ---------------- depthwise 3x3 conv PE on q ----------------
__global__ void __launch_bounds__(256)
dwconv_pe(const float* __restrict__ w, const float* __restrict__ bias)
{
    const int idx = blockIdx.x * 256 + threadIdx.x;
    const int c = idx & 255;
    const int n = (idx >> 8) & (NTOK - 1);
    const int b = idx >> 20;
    const int h = n >> 6;
    const int wd = n & 63;

    const float* q = gQ + (size_t)b * NTOK * CC;
    float acc = bias[c];
    #pragma unroll
    for (int di = -1; di <= 1; di++) {
        const int hh = h + di;
        if (hh < 0 || hh > 63) continue;
        #pragma unroll
        for (int dj = -1; dj <= 1; dj++) {
            const int w2 = wd + dj;
            if (w2 < 0 || w2 > 63) continue;
            acc = fmaf(q[(size_t)(hh * 64 + w2) * CC + c],
                       w[c * 9 + (di + 1) * 3 + (dj + 1)], acc);
        }
    }
    gPE[idx] = acc;
}

// ---------------- launch ----------------
extern "C" void kernel_launch(void* const* d_in, const int* in_sizes, int n_in,
                              void* d_out, int out_size)
{
    const float* x     = (const float*)d_in[0];
    const float* Wqkv  = (const float*)d_in[1];
    const float* Wgate = (const float*)d_in[2];
    const float* bgate = (const float*)d_in[3];
    const float* Wproj = (const float*)d_in[4];
    const float* pew   = (const float*)d_in[5];
    const float* peb   = (const float*)d_in[6];
    float* out = (float*)d_out;

    __half *pXh, *pWqkvh, *pWgateh, *pWprojh, *pTh;
    cudaGetSymbolAddress((void**)&pXh, gXh);
    cudaGetSymbolAddress((void**)&pWqkvh, gWqkvh);
    cudaGetSymbolAddress((void**)&pWgateh, gWgateh);
    cudaGetSymbolAddress((void**)&pWprojh, gWprojh);
    cudaGetSymbolAddress((void**)&pTh, gTh);

    constexpr int SMT = NSTAGE * (ASTG + BSTG_T);   // 75776
    cudaFuncSetAttribute(hgemm<0>, cudaFuncAttributeMaxDynamicSharedMemorySize, SMT);
    cudaFuncSetAttribute(hgemm<1>, cudaFuncAttributeMaxDynamicSharedMemorySize, SMT);
    cudaFuncSetAttribute(hgemm<4>, cudaFuncAttributeMaxDynamicSharedMemorySize, SMT);
    cudaFuncSetAttribute(flash_attn, cudaFuncAttributeMaxDynamicSharedMemorySize, FSMEM);

    // 0) converts
    const int cvt_n = N2_X + N2_QKV + 2 * N2_GW;
    convert_all<<<dim3((cvt_n + 255) / 256), 256>>>(x, Wqkv, Wgate, Wproj);
    // 1) qkv = x @ W_qkv -> gQ(fp32) + gQh/gKh/gVh
    hgemm<0><<<dim3(6,128,1), 256, SMT>>>(pXh, pWqkvh, nullptr, 256, 256, 768, nullptr);
    // 2) z = gelu(x @ W_gate + b)
    hgemm<1><<<dim3(2,128,1), 256, SMT>>>(pXh, pWgateh, nullptr, 256, 256, 256, bgate);
    // 3) PE depthwise conv from gQ
    dwconv_pe<<<dim3(BNTOK * CC / 256), 256>>>(pew, peb);
    // 4) fused attention: gTh = ((softmax(QK^T s) V) + PE) * Z
    flash_attn<<<dim3(64, BB), 256, FSMEM>>>();
    // 5) out = T @ W_proj
    hgemm<4><<<dim3(2,128,1), 256, SMT>>>(pTh, pWprojh, out, 256, 256, 256, nullptr);
}

// round 8
// speedup vs baseline: 1.1844x; 1.1844x over previous
#include <cuda_runtime.h>
#include <cuda_fp16.h>
#include <math.h>
#include <stdint.h>

#define BB 4
#define NTOK 4096
#define CC 256
#define BNTOK (BB * NTOK)   // 16384

// ---------------- static scratch ----------------
__device__ float  gQ  [(size_t)BNTOK * CC];          // fp32 Q for dwconv
__device__ __half gQh [(size_t)BNTOK * CC];
__device__ __half gKh [(size_t)BNTOK * CC];
__device__ __half gVh [(size_t)BNTOK * CC];
__device__ float  gZ  [(size_t)BNTOK * CC];
__device__ float  gPE [(size_t)BNTOK * CC];
__device__ __half gTh [(size_t)BNTOK * CC];
__device__ __half gPh [(size_t)BB * NTOK * NTOK];    // 128 MB: E = exp(scaled logits)
__device__ float  gL  [BNTOK];                       // row sums of E
__device__ __half gXh [(size_t)BNTOK * CC];
__device__ __half gWqkvh[CC * 3 * CC];
__device__ __half gWgateh[CC * CC];
__device__ __half gWprojh[CC * CC];

__device__ __forceinline__ void cpa16(uint32_t dst, const void* src) {
    asm volatile("cp.async.ca.shared.global [%0], [%1], 16;" :: "r"(dst), "l"(src));
}
__device__ __forceinline__ void ldmx4(uint32_t r[4], uint32_t addr) {
    asm volatile("ldmatrix.sync.aligned.m8n8.x4.shared.b16 {%0,%1,%2,%3}, [%4];"
                 : "=r"(r[0]), "=r"(r[1]), "=r"(r[2]), "=r"(r[3]) : "r"(addr));
}
__device__ __forceinline__ void ldmx2(uint32_t r[2], uint32_t addr) {
    asm volatile("ldmatrix.sync.aligned.m8n8.x2.shared.b16 {%0,%1}, [%2];"
                 : "=r"(r[0]), "=r"(r[1]) : "r"(addr));
}
__device__ __forceinline__ void ldmx2t(uint32_t r[2], uint32_t addr) {
    asm volatile("ldmatrix.sync.aligned.m8n8.x2.trans.shared.b16 {%0,%1}, [%2];"
                 : "=r"(r[0]), "=r"(r[1]) : "r"(addr));
}
__device__ __forceinline__ void mma_f16(float d[4], const uint32_t a[4],
                                        uint32_t b0, uint32_t b1) {
    asm volatile(
        "mma.sync.aligned.m16n8k16.row.col.f32.f16.f16.f32 "
        "{%0,%1,%2,%3}, {%4,%5,%6,%7}, {%8,%9}, {%0,%1,%2,%3};"
        : "+f"(d[0]), "+f"(d[1]), "+f"(d[2]), "+f"(d[3])
        : "r"(a[0]), "r"(a[1]), "r"(a[2]), "r"(a[3]), "r"(b0), "r"(b1));
}
__device__ __forceinline__ void waitN(int n) {
    if (n >= 2)      asm volatile("cp.async.wait_group 2;");
    else if (n == 1) asm volatile("cp.async.wait_group 1;");
    else             asm volatile("cp.async.wait_group 0;");
}

#define ASTG 10240                 // bytes per A stage: 128 rows * 80 B
#define BSTG_D 10240               // B direct stage
#define BSTG_T 8704                // B trans stage: 32 rows * 272 B
#define NSTAGE 4

// ======================================================================
// fp16 tensor-core GEMM, cp.async 4-stage, ldmatrix fragments. 256 thr.
// D[m][n] = sum_k A[m][k] * Bop[n][k]
//   TRB=1: B stored [N,K] (K contig)   TRB=0: B stored [K,N] (N contig)
// Tile 128x128, BK=32, 8 warps (2x4), warp tile 64x32.
// MODE 0: qkv split -> gQ(fp32) + gQh/gKh/gVh
// MODE 1: gZ = gelu(acc+bias)
// MODE 2: gPh = half(exp(acc*0.0625)); gL[row] += rowsum
// MODE 4: Out = acc (fp32)
// ======================================================================
template<int MODE, int TRB>
__global__ void __launch_bounds__(256, 2)
hgemm(const __half* __restrict__ A, const __half* __restrict__ B, float* __restrict__ Out,
      int K, int lda, int ldb, size_t sA, size_t sB, const float* __restrict__ bias)
{
    extern __shared__ __align__(16) char sm[];
    constexpr int BSTG = TRB ? BSTG_D : BSTG_T;
    const uint32_t smb = (uint32_t)__cvta_generic_to_shared(sm);
    const uint32_t aBase = smb;
    const uint32_t bBase = smb + NSTAGE * ASTG;

    const int tid  = threadIdx.x;
    const int wid  = tid >> 5;
    const int lane = tid & 31;
    const int g    = lane >> 2;
    const int t    = lane & 3;
    const int wm   = wid >> 2;
    const int wn   = wid & 3;

    const int bz     = blockIdx.z;
    const int rowBlk = blockIdx.y * 128;
    const int colBlk = blockIdx.x * 128;
    const __half* Ab = A + (size_t)bz * sA;
    const __half* Bb = B + (size_t)bz * sB;
    const int NC = K >> 5;

    float d[4][4][4];
    #pragma unroll
    for (int mi = 0; mi < 4; mi++)
        #pragma unroll
        for (int ni = 0; ni < 4; ni++)
            #pragma unroll
            for (int j = 0; j < 4; j++) d[mi][ni][j] = 0.0f;

    auto loadStage = [&](int c) {
        const int kt = c << 5;
        const int sb = c & (NSTAGE - 1);
        const uint32_t aS = aBase + sb * ASTG;
        #pragma unroll
        for (int j = 0; j < 2; j++) {
            const int task = tid + j * 256;
            const int row = task >> 2, ch = task & 3;
            cpa16(aS + row * 80 + ch * 16,
                  Ab + (size_t)(rowBlk + row) * lda + kt + ch * 8);
        }
        const uint32_t bS = bBase + sb * BSTG;
        if (TRB) {
            #pragma unroll
            for (int j = 0; j < 2; j++) {
                const int task = tid + j * 256;
                const int row = task >> 2, ch = task & 3;
                cpa16(bS + row * 80 + ch * 16,
                      Bb + (size_t)(colBlk + row) * ldb + kt + ch * 8);
            }
        } else {
            #pragma unroll
            for (int j = 0; j < 2; j++) {
                const int task = tid + j * 256;
                const int row = task >> 4, ch = task & 15;
                cpa16(bS + row * 272 + ch * 16,
                      Bb + (size_t)(kt + row) * ldb + colBlk + ch * 8);
            }
        }
        asm volatile("cp.async.commit_group;");
    };

    loadStage(0); loadStage(1); loadStage(2);

    for (int c = 0; c < NC; ++c) {
        waitN(NC - 1 - c);
        __syncthreads();
        if (c + 3 < NC) loadStage(c + 3);

        const int sb = c & (NSTAGE - 1);
        const uint32_t aS = aBase + sb * ASTG;
        const uint32_t bS = bBase + sb * BSTG;

        #pragma unroll
        for (int s = 0; s < 2; s++) {
            const int k0 = 16 * s;
            uint32_t a[4][4];
            #pragma unroll
            for (int mi = 0; mi < 4; mi++)
                ldmx4(a[mi], aS + ((wm * 64 + mi * 16 + (lane & 15)) * 40
                                   + k0 + (lane >> 4) * 8) * 2);
            uint32_t b[4][2];
            #pragma unroll
            for (int ni = 0; ni < 4; ni++) {
                if (TRB)
                    ldmx2(b[ni], bS + ((wn * 32 + ni * 8 + (lane & 7)) * 40
                                       + k0 + ((lane >> 3) & 1) * 8) * 2);
                else
                    ldmx2t(b[ni], bS + ((k0 + (lane & 15)) * 136 + wn * 32 + ni * 8) * 2);
            }
            #pragma unroll
            for (int mi = 0; mi < 4; mi++)
                #pragma unroll
                for (int ni = 0; ni < 4; ni++)
                    mma_f16(d[mi][ni], a[mi], b[ni][0], b[ni][1]);
        }
        __syncthreads();
    }

    // ---- epilogue ----
    #pragma unroll
    for (int mi = 0; mi < 4; mi++) {
        #pragma unroll
        for (int hf = 0; hf < 2; hf++) {
            const int r = rowBlk + wm * 64 + mi * 16 + g + hf * 8;

            if (MODE == 2) {
                float rsum = 0.0f;
                #pragma unroll
                for (int ni = 0; ni < 4; ni++) {
                    const int c = colBlk + wn * 32 + ni * 8 + 2 * t;
                    float e0 = __expf(d[mi][ni][2 * hf + 0] * 0.0625f);
                    float e1 = __expf(d[mi][ni][2 * hf + 1] * 0.0625f);
                    __half2 hv = __floats2half2_rn(e0, e1);
                    *(__half2*)&gPh[(size_t)bz * NTOK * NTOK + (size_t)r * NTOK + c] = hv;
                    rsum += __low2float(hv) + __high2float(hv);
                }
                rsum += __shfl_xor_sync(0xffffffffu, rsum, 1);
                rsum += __shfl_xor_sync(0xffffffffu, rsum, 2);
                if (t == 0) atomicAdd(&gL[bz * NTOK + r], rsum);
                continue;
            }

            #pragma unroll
            for (int ni = 0; ni < 4; ni++) {
                const int c = colBlk + wn * 32 + ni * 8 + 2 * t;
                float v0 = d[mi][ni][2 * hf + 0];
                float v1 = d[mi][ni][2 * hf + 1];

                if (MODE == 0) {
                    const int seg = c >> 8;
                    const int cc = c & 255;
                    const size_t idx = (size_t)r * CC + cc;
                    __half2 hv = __floats2half2_rn(v0, v1);
                    if (seg == 0) {
                        *(float2*)&gQ[idx] = make_float2(v0, v1);
                        *(__half2*)&gQh[idx] = hv;
                    } else if (seg == 1) {
                        *(__half2*)&gKh[idx] = hv;
                    } else {
                        *(__half2*)&gVh[idx] = hv;
                    }
                } else if (MODE == 1) {
                    float2 bb = *(const float2*)&bias[c];
                    float a0 = v0 + bb.x, a1 = v1 + bb.y;
                    float2 v;
                    v.x = 0.5f * a0 * (1.0f + erff(a0 * 0.70710678118654752f));
                    v.y = 0.5f * a1 * (1.0f + erff(a1 * 0.70710678118654752f));
                    *(float2*)&gZ[(size_t)r * CC + c] = v;
                } else {
                    *(float2*)&Out[(size_t)r * CC + c] = make_float2(v0, v1);
                }
            }
        }
    }
}

// ======================================================================
// PV GEMM: 512 threads, tile 128x256 (full N in one pass — E read once).
// 16 warps (wm 2 x wn 8), warp tile 64x32. B = V [K,N] trans path.
// Epilogue: gTh = half((acc/L + gPE) * gZ)
// ======================================================================
#define VSTR2 264                       // halves per V-stage row
#define BSTG2 (32 * VSTR2 * 2)          // 16896 bytes
#define SMPV (NSTAGE * (ASTG + BSTG2))  // 108544

__global__ void __launch_bounds__(512, 1)
hgemm_pv(const __half* __restrict__ A, const __half* __restrict__ B)
{
    extern __shared__ __align__(16) char sm[];
    const uint32_t smb = (uint32_t)__cvta_generic_to_shared(sm);
    const uint32_t aBase = smb;
    const uint32_t bBase = smb + NSTAGE * ASTG;

    const int tid  = threadIdx.x;
    const int wid  = tid >> 5;
    const int lane = tid & 31;
    const int g    = lane >> 2;
    const int t    = lane & 3;
    const int wm   = wid >> 3;      // 0..1
    const int wn   = wid & 7;       // 0..7

    const int bz     = blockIdx.z;
    const int rowBlk = blockIdx.y * 128;
    const __half* Ab = A + (size_t)bz * NTOK * NTOK;
    const __half* Bb = B + (size_t)bz * NTOK * CC;
    const int NC = NTOK >> 5;       // 128

    float d[4][4][4];
    #pragma unroll
    for (int mi = 0; mi < 4; mi++)
        #pragma unroll
        for (int ni = 0; ni < 4; ni++)
            #pragma unroll
            for (int j = 0; j < 4; j++) d[mi][ni][j] = 0.0f;

    auto loadStage = [&](int c) {
        const int kt = c << 5;
        const int sb = c & (NSTAGE - 1);
        const uint32_t aS = aBase + sb * ASTG;
        {   // A: 128 rows x 4 chunks = 512 tasks
            const int row = tid >> 2, ch = tid & 3;
            cpa16(aS + row * 80 + ch * 16,
                  Ab + (size_t)(rowBlk + row) * NTOK + kt + ch * 8);
        }
        const uint32_t bS = bBase + sb * BSTG2;
        #pragma unroll
        for (int j = 0; j < 2; j++) {   // B: 32 rows x 32 chunks = 1024 tasks
            const int task = tid + j * 512;
            const int row = task >> 5, ch = task & 31;
            cpa16(bS + (row * VSTR2 + ch * 8) * 2,
                  Bb + (size_t)(kt + row) * CC + ch * 8);
        }
        asm volatile("cp.async.commit_group;");
    };

    loadStage(0); loadStage(1); loadStage(2);

    for (int c = 0; c < NC; ++c) {
        waitN(NC - 1 - c);
        __syncthreads();
        if (c + 3 < NC) loadStage(c + 3);

        const int sb = c & (NSTAGE - 1);
        const uint32_t aS = aBase + sb * ASTG;
        const uint32_t bS = bBase + sb * BSTG2;

        #pragma unroll
        for (int s = 0; s < 2; s++) {
            const int k0 = 16 * s;
            uint32_t a[4][4];
            #pragma unroll
            for (int mi = 0; mi < 4; mi++)
                ldmx4(a[mi], aS + ((wm * 64 + mi * 16 + (lane & 15)) * 40
                                   + k0 + (lane >> 4) * 8) * 2);
            uint32_t b[4][2];
            #pragma unroll
            for (int ni = 0; ni < 4; ni++)
                ldmx2t(b[ni], bS + ((k0 + (lane & 15)) * VSTR2 + wn * 32 + ni * 8) * 2);
            #pragma unroll
            for (int mi = 0; mi < 4; mi++)
                #pragma unroll
                for (int ni = 0; ni < 4; ni++)
                    mma_f16(d[mi][ni], a[mi], b[ni][0], b[ni][1]);
        }
        __syncthreads();
    }

    #pragma unroll
    for (int mi = 0; mi < 4; mi++) {
        #pragma unroll
        for (int hf = 0; hf < 2; hf++) {
            const int r = rowBlk + wm * 64 + mi * 16 + g + hf * 8;
            const float invL = 1.0f / gL[bz * NTOK + r];
            #pragma unroll
            for (int ni = 0; ni < 4; ni++) {
                const int c = wn * 32 + ni * 8 + 2 * t;
                const size_t idx = ((size_t)(bz * NTOK + r)) * CC + c;
                float2 pe = *(const float2*)&gPE[idx];
                float2 zz = *(const float2*)&gZ[idx];
                float v0 = d[mi][ni][2 * hf + 0] * invL;
                float v1 = d[mi][ni][2 * hf + 1] * invL;
                *(__half2*)&gTh[idx] = __floats2half2_rn((v0 + pe.x) * zz.x,
                                                         (v1 + pe.y) * zz.y);
            }
        }
    }
}

// ---------------- fused convert (x + 3 weights -> fp16) + zero gL ----------------
#define N2_X   (BNTOK * CC / 2)
#define N2_QKV (CC * 3 * CC / 2)
#define N2_GW  (CC * CC / 2)
__global__ void __launch_bounds__(256)
convert_all(const float* __restrict__ x, const float* __restrict__ Wqkv,
            const float* __restrict__ Wgate, const float* __restrict__ Wproj)
{
    int i = blockIdx.x * 256 + threadIdx.x;
    if (i < BNTOK) gL[i] = 0.0f;

    const float* src; __half* dst; int off;
    if (i < N2_X)                        { src = x;     dst = gXh;     off = i; }
    else if ((i -= N2_X) < N2_QKV)       { src = Wqkv;  dst = gWqkvh;  off = i; }
    else if ((i -= N2_QKV) < N2_GW)      { src = Wgate; dst = gWgateh; off = i; }
    else if ((i -= N2_GW) < N2_GW)       { src = Wproj; dst = gWprojh; off = i; }
    else return;
    float2 v = *(const float2*)(src + 2 * off);
    *(__half2*)(dst + 2 * off) = __floats2half2_rn(v.x, v.y);
}

// ---------------- depthwise 3x3 conv PE on q ----------------
__global__ void __launch_bounds__(256)
dwconv_pe(const float* __restrict__ w, const float* __restrict__ bias)
{
    const int idx = blockIdx.x * 256 + threadIdx.x;
    const int c = idx & 255;
    const int n = (idx >> 8) & (NTOK - 1);
    const int b = idx >> 20;
    const int h = n >> 6;
    const int wd = n & 63;

    const float* q = gQ + (size_t)b * NTOK * CC;
    float acc = bias[c];
    #pragma unroll
    for (int di = -1; di <= 1; di++) {
        const int hh = h + di;
        if (hh < 0 || hh > 63) continue;
        #pragma unroll
        for (int dj = -1; dj <= 1; dj++) {
            const int w2 = wd + dj;
            if (w2 < 0 || w2 > 63) continue;
            acc = fmaf(q[(size_t)(hh * 64 + w2) * CC + c],
                       w[c * 9 + (di + 1) * 3 + (dj + 1)], acc);
        }
    }
    gPE[idx] = acc;
}

// ---------------- launch ----------------
extern "C" void kernel_launch(void* const* d_in, const int* in_sizes, int n_in,
                              void* d_out, int out_size)
{
    const float* x     = (const float*)d_in[0];
    const float* Wqkv  = (const float*)d_in[1];
    const float* Wgate = (const float*)d_in[2];
    const float* bgate = (const float*)d_in[3];
    const float* Wproj = (const float*)d_in[4];
    const float* pew   = (const float*)d_in[5];
    const float* peb   = (const float*)d_in[6];
    float* out = (float*)d_out;

    __half *pXh, *pWqkvh, *pWgateh, *pWprojh, *pQh, *pKh, *pVh, *pPh, *pTh;
    cudaGetSymbolAddress((void**)&pXh, gXh);
    cudaGetSymbolAddress((void**)&pWqkvh, gWqkvh);
    cudaGetSymbolAddress((void**)&pWgateh, gWgateh);
    cudaGetSymbolAddress((void**)&pWprojh, gWprojh);
    cudaGetSymbolAddress((void**)&pQh, gQh);
    cudaGetSymbolAddress((void**)&pKh, gKh);
    cudaGetSymbolAddress((void**)&pVh, gVh);
    cudaGetSymbolAddress((void**)&pPh, gPh);
    cudaGetSymbolAddress((void**)&pTh, gTh);

    constexpr int SMD = NSTAGE * (ASTG + BSTG_D);   // 81920
    constexpr int SMT = NSTAGE * (ASTG + BSTG_T);   // 75776
    cudaFuncSetAttribute(hgemm<0,0>, cudaFuncAttributeMaxDynamicSharedMemorySize, SMT);
    cudaFuncSetAttribute(hgemm<1,0>, cudaFuncAttributeMaxDynamicSharedMemorySize, SMT);
    cudaFuncSetAttribute(hgemm<2,1>, cudaFuncAttributeMaxDynamicSharedMemorySize, SMD);
    cudaFuncSetAttribute(hgemm<4,0>, cudaFuncAttributeMaxDynamicSharedMemorySize, SMT);
    cudaFuncSetAttribute(hgemm_pv, cudaFuncAttributeMaxDynamicSharedMemorySize, SMPV);

    // 0) converts + zero row sums
    const int cvt_n = N2_X + N2_QKV + 2 * N2_GW;
    convert_all<<<dim3((cvt_n + 255) / 256), 256>>>(x, Wqkv, Wgate, Wproj);

    // 1) qkv = x @ W_qkv -> gQ(fp32) + gQh/gKh/gVh
    hgemm<0,0><<<dim3(6,128,1), 256, SMT>>>(pXh, pWqkvh, nullptr, 256, 256, 768, 0, 0, nullptr);
    // 2) z = gelu(x @ W_gate + b)
    hgemm<1,0><<<dim3(2,128,1), 256, SMT>>>(pXh, pWgateh, nullptr, 256, 256, 256, 0, 0, bgate);
    // 3) PE depthwise conv from gQ
    dwconv_pe<<<dim3(BNTOK * CC / 256), 256>>>(pew, peb);
    // 4) E = exp(scale * Q K^T), row sums into gL
    hgemm<2,1><<<dim3(32,32,BB), 256, SMD>>>(pQh, pKh, nullptr, 256, 256, 256,
                                             (size_t)NTOK * CC, (size_t)NTOK * CC, nullptr);
    // 5) T = (E @ V / L + PE) * Z -> gTh   (single wave, E read once)
    hgemm_pv<<<dim3(1,32,BB), 512, SMPV>>>(pPh, pVh);
    // 6) out = T @ W_proj
    hgemm<4,0><<<dim3(2,128,1), 256, SMT>>>(pTh, pWprojh, out, 256, 256, 256, 0, 0, nullptr);
}

// round 9
// speedup vs baseline: 1.1942x; 1.0084x over previous
#include <cuda_runtime.h>
#include <cuda_fp16.h>
#include <math.h>
#include <stdint.h>

#define BB 4
#define NTOK 4096
#define CC 256
#define BNTOK (BB * NTOK)   // 16384

// ---------------- static scratch ----------------
__device__ __half gQh [(size_t)BNTOK * CC];
__device__ __half gKh [(size_t)BNTOK * CC];
__device__ __half gVh [(size_t)BNTOK * CC];
__device__ float  gZ  [(size_t)BNTOK * CC];
__device__ float  gPE [(size_t)BNTOK * CC];
__device__ __half gTh [(size_t)BNTOK * CC];
__device__ __half gPh [(size_t)BB * NTOK * NTOK];    // 128 MB: E = exp(scaled logits)
__device__ float  gL  [BNTOK];                       // row sums of E
__device__ __half gXh [(size_t)BNTOK * CC];
__device__ __half gWch [CC * 1024];                  // [K=256][N=1024]: qkv(768) | gate(256)
__device__ __half gWprojh[CC * CC];

__device__ __forceinline__ void cpa16(uint32_t dst, const void* src) {
    asm volatile("cp.async.ca.shared.global [%0], [%1], 16;" :: "r"(dst), "l"(src));
}
__device__ __forceinline__ void ldmx4(uint32_t r[4], uint32_t addr) {
    asm volatile("ldmatrix.sync.aligned.m8n8.x4.shared.b16 {%0,%1,%2,%3}, [%4];"
                 : "=r"(r[0]), "=r"(r[1]), "=r"(r[2]), "=r"(r[3]) : "r"(addr));
}
__device__ __forceinline__ void ldmx2(uint32_t r[2], uint32_t addr) {
    asm volatile("ldmatrix.sync.aligned.m8n8.x2.shared.b16 {%0,%1}, [%2];"
                 : "=r"(r[0]), "=r"(r[1]) : "r"(addr));
}
__device__ __forceinline__ void ldmx2t(uint32_t r[2], uint32_t addr) {
    asm volatile("ldmatrix.sync.aligned.m8n8.x2.trans.shared.b16 {%0,%1}, [%2];"
                 : "=r"(r[0]), "=r"(r[1]) : "r"(addr));
}
__device__ __forceinline__ void mma_f16(float d[4], const uint32_t a[4],
                                        uint32_t b0, uint32_t b1) {
    asm volatile(
        "mma.sync.aligned.m16n8k16.row.col.f32.f16.f16.f32 "
        "{%0,%1,%2,%3}, {%4,%5,%6,%7}, {%8,%9}, {%0,%1,%2,%3};"
        : "+f"(d[0]), "+f"(d[1]), "+f"(d[2]), "+f"(d[3])
        : "r"(a[0]), "r"(a[1]), "r"(a[2]), "r"(a[3]), "r"(b0), "r"(b1));
}
__device__ __forceinline__ void waitN(int n) {
    if (n >= 2)      asm volatile("cp.async.wait_group 2;");
    else if (n == 1) asm volatile("cp.async.wait_group 1;");
    else             asm volatile("cp.async.wait_group 0;");
}

#define ASTG 10240                 // A stage: 128 rows * 80 B
#define BSTG_D 10240               // B direct stage (128 rows * 80 B)
#define BSTG_T 8704                // B trans stage: 32 rows * 272 B
#define NSTAGE 4

// ======================================================================
// fp16 GEMM, 256 thr, tile 128x128, cp.async 4-stage.
// TRB=1: B [N,K]; TRB=0: B [K,N].
// MODE 0: merged qkv+gate; col segs: 0=Qh 1=Kh 2=Vh 3=gZ(gelu+bias)
// MODE 2: gPh = half(exp(acc*0.0625)); gL[row] += rowsum
// MODE 4: Out = acc (fp32)
// ======================================================================
template<int MODE, int TRB>
__global__ void __launch_bounds__(256, 2)
hgemm(const __half* __restrict__ A, const __half* __restrict__ B, float* __restrict__ Out,
      int K, int lda, int ldb, size_t sA, size_t sB, const float* __restrict__ bias)
{
    extern __shared__ __align__(16) char sm[];
    constexpr int BSTG = TRB ? BSTG_D : BSTG_T;
    const uint32_t smb = (uint32_t)__cvta_generic_to_shared(sm);
    const uint32_t aBase = smb;
    const uint32_t bBase = smb + NSTAGE * ASTG;

    const int tid  = threadIdx.x;
    const int wid  = tid >> 5;
    const int lane = tid & 31;
    const int g    = lane >> 2;
    const int t    = lane & 3;
    const int wm   = wid >> 2;
    const int wn   = wid & 3;

    const int bz     = blockIdx.z;
    const int rowBlk = blockIdx.y * 128;
    const int colBlk = blockIdx.x * 128;
    const __half* Ab = A + (size_t)bz * sA;
    const __half* Bb = B + (size_t)bz * sB;
    const int NC = K >> 5;

    float d[4][4][4];
    #pragma unroll
    for (int mi = 0; mi < 4; mi++)
        #pragma unroll
        for (int ni = 0; ni < 4; ni++)
            #pragma unroll
            for (int j = 0; j < 4; j++) d[mi][ni][j] = 0.0f;

    auto loadStage = [&](int c) {
        const int kt = c << 5;
        const int sb = c & (NSTAGE - 1);
        const uint32_t aS = aBase + sb * ASTG;
        #pragma unroll
        for (int j = 0; j < 2; j++) {
            const int task = tid + j * 256;
            const int row = task >> 2, ch = task & 3;
            cpa16(aS + row * 80 + ch * 16,
                  Ab + (size_t)(rowBlk + row) * lda + kt + ch * 8);
        }
        const uint32_t bS = bBase + sb * BSTG;
        if (TRB) {
            #pragma unroll
            for (int j = 0; j < 2; j++) {
                const int task = tid + j * 256;
                const int row = task >> 2, ch = task & 3;
                cpa16(bS + row * 80 + ch * 16,
                      Bb + (size_t)(colBlk + row) * ldb + kt + ch * 8);
            }
        } else {
            #pragma unroll
            for (int j = 0; j < 2; j++) {
                const int task = tid + j * 256;
                const int row = task >> 4, ch = task & 15;
                cpa16(bS + row * 272 + ch * 16,
                      Bb + (size_t)(kt + row) * ldb + colBlk + ch * 8);
            }
        }
        asm volatile("cp.async.commit_group;");
    };

    loadStage(0); loadStage(1); loadStage(2);

    for (int c = 0; c < NC; ++c) {
        waitN(NC - 1 - c);
        __syncthreads();
        if (c + 3 < NC) loadStage(c + 3);

        const int sb = c & (NSTAGE - 1);
        const uint32_t aS = aBase + sb * ASTG;
        const uint32_t bS = bBase + sb * BSTG;

        #pragma unroll
        for (int s = 0; s < 2; s++) {
            const int k0 = 16 * s;
            uint32_t a[4][4];
            #pragma unroll
            for (int mi = 0; mi < 4; mi++)
                ldmx4(a[mi], aS + ((wm * 64 + mi * 16 + (lane & 15)) * 40
                                   + k0 + (lane >> 4) * 8) * 2);
            uint32_t b[4][2];
            #pragma unroll
            for (int ni = 0; ni < 4; ni++) {
                if (TRB)
                    ldmx2(b[ni], bS + ((wn * 32 + ni * 8 + (lane & 7)) * 40
                                       + k0 + ((lane >> 3) & 1) * 8) * 2);
                else
                    ldmx2t(b[ni], bS + ((k0 + (lane & 15)) * 136 + wn * 32 + ni * 8) * 2);
            }
            #pragma unroll
            for (int mi = 0; mi < 4; mi++)
                #pragma unroll
                for (int ni = 0; ni < 4; ni++)
                    mma_f16(d[mi][ni], a[mi], b[ni][0], b[ni][1]);
        }
        __syncthreads();
    }

    // ---- epilogue ----
    #pragma unroll
    for (int mi = 0; mi < 4; mi++) {
        #pragma unroll
        for (int hf = 0; hf < 2; hf++) {
            const int r = rowBlk + wm * 64 + mi * 16 + g + hf * 8;

            if (MODE == 2) {
                float rsum = 0.0f;
                #pragma unroll
                for (int ni = 0; ni < 4; ni++) {
                    const int c = colBlk + wn * 32 + ni * 8 + 2 * t;
                    float e0 = __expf(d[mi][ni][2 * hf + 0] * 0.0625f);
                    float e1 = __expf(d[mi][ni][2 * hf + 1] * 0.0625f);
                    __half2 hv = __floats2half2_rn(e0, e1);
                    *(__half2*)&gPh[(size_t)bz * NTOK * NTOK + (size_t)r * NTOK + c] = hv;
                    rsum += __low2float(hv) + __high2float(hv);
                }
                rsum += __shfl_xor_sync(0xffffffffu, rsum, 1);
                rsum += __shfl_xor_sync(0xffffffffu, rsum, 2);
                if (t == 0) atomicAdd(&gL[bz * NTOK + r], rsum);
                continue;
            }

            #pragma unroll
            for (int ni = 0; ni < 4; ni++) {
                const int c = colBlk + wn * 32 + ni * 8 + 2 * t;
                float v0 = d[mi][ni][2 * hf + 0];
                float v1 = d[mi][ni][2 * hf + 1];

                if (MODE == 0) {
                    const int seg = c >> 8;
                    const int cc = c & 255;
                    const size_t idx = (size_t)r * CC + cc;
                    if (seg == 3) {
                        float2 bb = *(const float2*)&bias[cc];
                        float a0 = v0 + bb.x, a1 = v1 + bb.y;
                        float2 v;
                        v.x = 0.5f * a0 * (1.0f + erff(a0 * 0.70710678118654752f));
                        v.y = 0.5f * a1 * (1.0f + erff(a1 * 0.70710678118654752f));
                        *(float2*)&gZ[idx] = v;
                    } else {
                        __half2 hv = __floats2half2_rn(v0, v1);
                        __half* dst = (seg == 0) ? gQh : (seg == 1) ? gKh : gVh;
                        *(__half2*)&dst[idx] = hv;
                    }
                } else {
                    *(float2*)&Out[(size_t)r * CC + c] = make_float2(v0, v1);
                }
            }
        }
    }
}

// ======================================================================
// PV GEMM: 256 thr, tile 64x256 (full N — E read once), grid 256 CTAs.
// 8 warps (1 x 8), warp tile 64x32. B = V [K,N] trans path, stride 264.
// Epilogue: gTh = half((acc/L + gPE) * gZ)
// ======================================================================
#define ASTG64 5120                     // 64 rows * 80 B
#define VSTR2 264                       // halves per V-stage row
#define BSTG2 (32 * VSTR2 * 2)          // 16896 bytes
#define SMPV (NSTAGE * (ASTG64 + BSTG2))  // 88064

__global__ void __launch_bounds__(256, 2)
hgemm_pv(const __half* __restrict__ A, const __half* __restrict__ B)
{
    extern __shared__ __align__(16) char sm[];
    const uint32_t smb = (uint32_t)__cvta_generic_to_shared(sm);
    const uint32_t aBase = smb;
    const uint32_t bBase = smb + NSTAGE * ASTG64;

    const int tid  = threadIdx.x;
    const int wn   = tid >> 5;      // warp = column block 0..7
    const int lane = tid & 31;
    const int g    = lane >> 2;
    const int t    = lane & 3;

    const int bz     = blockIdx.z;
    const int rowBlk = blockIdx.y * 64;
    const __half* Ab = A + (size_t)bz * NTOK * NTOK;
    const __half* Bb = B + (size_t)bz * NTOK * CC;
    const int NC = NTOK >> 5;       // 128

    float d[4][4][4];
    #pragma unroll
    for (int mi = 0; mi < 4; mi++)
        #pragma unroll
        for (int ni = 0; ni < 4; ni++)
            #pragma unroll
            for (int j = 0; j < 4; j++) d[mi][ni][j] = 0.0f;

    auto loadStage = [&](int c) {
        const int kt = c << 5;
        const int sb = c & (NSTAGE - 1);
        const uint32_t aS = aBase + sb * ASTG64;
        {   // A: 64 rows x 4 chunks = 256 tasks
            const int row = tid >> 2, ch = tid & 3;
            cpa16(aS + row * 80 + ch * 16,
                  Ab + (size_t)(rowBlk + row) * NTOK + kt + ch * 8);
        }
        const uint32_t bS = bBase + sb * BSTG2;
        #pragma unroll
        for (int j = 0; j < 4; j++) {   // B: 32 rows x 32 chunks = 1024 tasks
            const int task = tid + j * 256;
            const int row = task >> 5, ch = task & 31;
            cpa16(bS + (row * VSTR2 + ch * 8) * 2,
                  Bb + (size_t)(kt + row) * CC + ch * 8);
        }
        asm volatile("cp.async.commit_group;");
    };

    loadStage(0); loadStage(1); loadStage(2);

    for (int c = 0; c < NC; ++c) {
        waitN(NC - 1 - c);
        __syncthreads();
        if (c + 3 < NC) loadStage(c + 3);

        const int sb = c & (NSTAGE - 1);
        const uint32_t aS = aBase + sb * ASTG64;
        const uint32_t bS = bBase + sb * BSTG2;

        #pragma unroll
        for (int s = 0; s < 2; s++) {
            const int k0 = 16 * s;
            uint32_t a[4][4];
            #pragma unroll
            for (int mi = 0; mi < 4; mi++)
                ldmx4(a[mi], aS + ((mi * 16 + (lane & 15)) * 40
                                   + k0 + (lane >> 4) * 8) * 2);
            uint32_t b[4][2];
            #pragma unroll
            for (int ni = 0; ni < 4; ni++)
                ldmx2t(b[ni], bS + ((k0 + (lane & 15)) * VSTR2 + wn * 32 + ni * 8) * 2);
            #pragma unroll
            for (int mi = 0; mi < 4; mi++)
                #pragma unroll
                for (int ni = 0; ni < 4; ni++)
                    mma_f16(d[mi][ni], a[mi], b[ni][0], b[ni][1]);
        }
        __syncthreads();
    }

    #pragma unroll
    for (int mi = 0; mi < 4; mi++) {
        #pragma unroll
        for (int hf = 0; hf < 2; hf++) {
            const int r = rowBlk + mi * 16 + g + hf * 8;
            const float invL = 1.0f / gL[bz * NTOK + r];
            #pragma unroll
            for (int ni = 0; ni < 4; ni++) {
                const int c = wn * 32 + ni * 8 + 2 * t;
                const size_t idx = ((size_t)(bz * NTOK + r)) * CC + c;
                float2 pe = *(const float2*)&gPE[idx];
                float2 zz = *(const float2*)&gZ[idx];
                float v0 = d[mi][ni][2 * hf + 0] * invL;
                float v1 = d[mi][ni][2 * hf + 1] * invL;
                *(__half2*)&gTh[idx] = __floats2half2_rn((v0 + pe.x) * zz.x,
                                                         (v1 + pe.y) * zz.y);
            }
        }
    }
}

// ---------------- fused convert + zero gL ----------------
// x -> gXh; [Wqkv|Wgate] -> gWch (N=1024 combined); Wproj -> gWprojh
#define N2_X   (BNTOK * CC / 2)        // 2097152
#define N2_WC  (CC * 1024 / 2)         // 131072
#define N2_GW  (CC * CC / 2)           // 32768
__global__ void __launch_bounds__(256)
convert_all(const float* __restrict__ x, const float* __restrict__ Wqkv,
            const float* __restrict__ Wgate, const float* __restrict__ Wproj)
{
    int i = blockIdx.x * 256 + threadIdx.x;
    if (i < BNTOK) gL[i] = 0.0f;

    if (i < N2_X) {
        float2 v = *(const float2*)(x + 2 * i);
        *(__half2*)(gXh + 2 * i) = __floats2half2_rn(v.x, v.y);
        return;
    }
    i -= N2_X;
    if (i < N2_WC) {
        const int h = 2 * i;
        const int k = h >> 10, n = h & 1023;
        const float* src = (n < 768) ? (Wqkv + (size_t)k * 768 + n)
                                     : (Wgate + (size_t)k * 256 + (n - 768));
        float2 v = *(const float2*)src;
        *(__half2*)(gWch + h) = __floats2half2_rn(v.x, v.y);
        return;
    }
    i -= N2_WC;
    if (i < N2_GW) {
        float2 v = *(const float2*)(Wproj + 2 * i);
        *(__half2*)(gWprojh + 2 * i) = __floats2half2_rn(v.x, v.y);
    }
}

// ---------------- depthwise 3x3 conv PE on q (reads fp16 Q) ----------------
__global__ void __launch_bounds__(256)
dwconv_pe(const float* __restrict__ w, const float* __restrict__ bias)
{
    const int idx = blockIdx.x * 256 + threadIdx.x;
    const int c = idx & 255;
    const int n = (idx >> 8) & (NTOK - 1);
    const int b = idx >> 20;
    const int h = n >> 6;
    const int wd = n & 63;

    const __half* q = gQh + (size_t)b * NTOK * CC;
    float acc = bias[c];
    #pragma unroll
    for (int di = -1; di <= 1; di++) {
        const int hh = h + di;
        if (hh < 0 || hh > 63) continue;
        #pragma unroll
        for (int dj = -1; dj <= 1; dj++) {
            const int w2 = wd + dj;
            if (w2 < 0 || w2 > 63) continue;
            acc = fmaf(__half2float(q[(size_t)(hh * 64 + w2) * CC + c]),
                       w[c * 9 + (di + 1) * 3 + (dj + 1)], acc);
        }
    }
    gPE[idx] = acc;
}

// ---------------- launch ----------------
extern "C" void kernel_launch(void* const* d_in, const int* in_sizes, int n_in,
                              void* d_out, int out_size)
{
    const float* x     = (const float*)d_in[0];
    const float* Wqkv  = (const float*)d_in[1];
    const float* Wgate = (const float*)d_in[2];
    const float* bgate = (const float*)d_in[3];
    const float* Wproj = (const float*)d_in[4];
    const float* pew   = (const float*)d_in[5];
    const float* peb   = (const float*)d_in[6];
    float* out = (float*)d_out;

    __half *pXh, *pWch, *pWprojh, *pQh, *pKh, *pVh, *pPh, *pTh;
    cudaGetSymbolAddress((void**)&pXh, gXh);
    cudaGetSymbolAddress((void**)&pWch, gWch);
    cudaGetSymbolAddress((void**)&pWprojh, gWprojh);
    cudaGetSymbolAddress((void**)&pQh, gQh);
    cudaGetSymbolAddress((void**)&pKh, gKh);
    cudaGetSymbolAddress((void**)&pVh, gVh);
    cudaGetSymbolAddress((void**)&pPh, gPh);
    cudaGetSymbolAddress((void**)&pTh, gTh);

    constexpr int SMD = NSTAGE * (ASTG + BSTG_D);   // 81920
    constexpr int SMT = NSTAGE * (ASTG + BSTG_T);   // 75776
    cudaFuncSetAttribute(hgemm<0,0>, cudaFuncAttributeMaxDynamicSharedMemorySize, SMT);
    cudaFuncSetAttribute(hgemm<2,1>, cudaFuncAttributeMaxDynamicSharedMemorySize, SMD);
    cudaFuncSetAttribute(hgemm<4,0>, cudaFuncAttributeMaxDynamicSharedMemorySize, SMT);
    cudaFuncSetAttribute(hgemm_pv, cudaFuncAttributeMaxDynamicSharedMemorySize, SMPV);

    // 0) converts + zero row sums
    const int cvt_n = N2_X + N2_WC + N2_GW;
    convert_all<<<dim3((cvt_n + 255) / 256), 256>>>(x, Wqkv, Wgate, Wproj);

    // 1) merged qkv+gate: [16384,256] x [256,1024] -> Qh/Kh/Vh/gZ
    hgemm<0,0><<<dim3(8,128,1), 256, SMT>>>(pXh, pWch, nullptr, 256, 256, 1024, 0, 0, bgate);
    // 2) PE depthwise conv from gQh
    dwconv_pe<<<dim3(BNTOK * CC / 256), 256>>>(pew, peb);
    // 3) E = exp(scale * Q K^T), row sums into gL
    hgemm<2,1><<<dim3(32,32,BB), 256, SMD>>>(pQh, pKh, nullptr, 256, 256, 256,
                                             (size_t)NTOK * CC, (size_t)NTOK * CC, nullptr);
    // 4) T = (E @ V / L + PE) * Z -> gTh  (64x256 tiles, E read once, 256 CTAs)
    hgemm_pv<<<dim3(1,64,BB), 256, SMPV>>>(pPh, pVh);
    // 5) out = T @ W_proj
    hgemm<4,0><<<dim3(2,128,1), 256, SMT>>>(pTh, pWprojh, out, 256, 256, 256, 0, 0, nullptr);
}